// round 13
// baseline (speedup 1.0000x reference)
#include <cuda_runtime.h>
#include <cstdint>

#define Hh 256
#define Tt 187
#define Bb 1024
#define Cc 5
#define CLW 4
#define MBc 32                    // batch rows per cluster
#define THR 256
#define NCTA ((Bb / MBc) * CLW)   // 128 CTAs = 32 clusters x 4

// Packed weights: [k/4][j][4] so lane j loads 16B of 4 consecutive k's,
// coalesced across lanes (lanes = consecutive j).
__device__ float g_Wp0[Hh * Hh];
__device__ float g_Wpih1[Hh * Hh];
__device__ float g_Wp1[Hh * Hh];

__global__ void pack_kernel(const float* __restrict__ W_hh0,
                            const float* __restrict__ W_ih1,
                            const float* __restrict__ W_hh1) {
    int j = blockIdx.x, k = threadIdx.x;
    int src = j * Hh + k;
    int dst = ((k >> 2) * Hh + j) * 4 + (k & 3);
    g_Wp0[dst]   = W_hh0[src];
    g_Wpih1[dst] = W_ih1[src];
    g_Wp1[dst]   = W_hh1[src];
}

union F2U { unsigned long long u; float2 f; };

__device__ __forceinline__ unsigned long long f32x2_fma(
    unsigned long long a, unsigned long long b, unsigned long long c) {
    unsigned long long d;
    asm("fma.rn.f32x2 %0, %1, %2, %3;" : "=l"(d) : "l"(a), "l"(b), "l"(c));
    return d;
}

__device__ __forceinline__ uint32_t smem_u32(const void* p) {
    uint32_t a;
    asm("{ .reg .u64 t; cvta.to.shared.u64 t, %1; cvt.u32.u64 %0, t; }"
        : "=r"(a) : "l"(p));
    return a;
}

// 16B store to the same smem offset in CTA `peer` of this cluster.
__device__ __forceinline__ void dsmem_st128(uint32_t laddr, uint32_t peer,
                                            float4 v) {
    asm volatile(
        "{\n\t.reg .b32 ra;\n\t"
        "mapa.shared::cluster.u32 ra, %0, %1;\n\t"
        "st.shared::cluster.v4.f32 [ra], {%2, %3, %4, %5};\n\t}"
        :: "r"(laddr), "r"(peer), "f"(v.x), "f"(v.y), "f"(v.z), "f"(v.w)
        : "memory");
}

__device__ __forceinline__ void cl_arrive() {
    asm volatile("barrier.cluster.arrive.aligned;" ::: "memory");
}
__device__ __forceinline__ void cl_wait() {
    asm volatile("barrier.cluster.wait.aligned;" ::: "memory");
}

struct Smem {
    float wa[64][64][4];        // W_ih1 col-slice  64 KB  [k4][col][4]
    float wb[64][64][4];        // W_hh1 col-slice  64 KB
    float h0[MBc][Hh];          // 32 KB (full h, replicated per CTA)
    float h1[MBc][Hh];          // 32 KB
    float part[2][MBc][64];     // 16 KB  [kg][row][local col]
    float wih0s[64], bias0s[64], bias1s[64];
};                              // ~209 KB

__global__ void __launch_bounds__(THR, 1) __cluster_dims__(CLW, 1, 1)
rnn_cl4_kernel(
    const float* __restrict__ x,
    const float* __restrict__ W_ih0,
    const float* __restrict__ b_ih0, const float* __restrict__ b_hh0,
    const float* __restrict__ b_ih1, const float* __restrict__ b_hh1,
    const float* __restrict__ W_fc,  const float* __restrict__ b_fc,
    float* __restrict__ out)
{
    extern __shared__ __align__(16) char raw[];
    Smem& S = *reinterpret_cast<Smem*>(raw);

    const int t    = threadIdx.x;
    const int lane = t & 31;           // local col jj; second col jj+32
    const int w    = t >> 5;
    const int kg   = w & 1;            // k half (32 k4 each)
    const int rg   = w >> 1;           // rows [8rg, 8rg+8)
    uint32_t rank;
    asm("mov.u32 %0, %%cluster_ctarank;" : "=r"(rank));
    const int colbase = (int)rank * 64;
    const int b0      = (blockIdx.x / CLW) * MBc;

    // ---- load this CTA's layer-1 weight slices into smem (once) ---------
    for (int i = t; i < 64 * 256; i += THR) {
        int k4 = i >> 8, rem = i & 255;          // rem = col*4 + kk
        int col = rem >> 2, kk = rem & 3;
        int g = (k4 * Hh + colbase + col) * 4 + kk;
        (&S.wa[0][0][0])[i] = g_Wpih1[g];
        (&S.wb[0][0][0])[i] = g_Wp1[g];
    }
    if (t < 64) {
        S.wih0s[t]  = W_ih0[colbase + t];
        S.bias0s[t] = b_ih0[colbase + t] + b_hh0[colbase + t];
        S.bias1s[t] = b_ih1[colbase + t] + b_hh1[colbase + t];
    }
    for (int i = t; i < MBc * Hh; i += THR) {
        (&S.h0[0][0])[i] = 0.f;
        (&S.h1[0][0])[i] = 0.f;
    }
    __syncthreads();
    cl_arrive(); cl_wait();

    const int k4lo = kg * 32;
    // reduce role: cols [colbase+4q, +4), rows {2p, 2p+1}
    const int q = t & 15, p = t >> 4;

    for (int step = 0; step < Tt; ++step) {
        const float xv0 = x[(b0 + 2 * p) * Tt + step];
        const float xv1 = x[(b0 + 2 * p + 1) * Tt + step];

        // ===== layer 0 partials (W_hh0 streamed from L2) =================
        unsigned long long a0[8], a1[8];
        #pragma unroll
        for (int r = 0; r < 8; ++r) { a0[r] = 0ULL; a1[r] = 0ULL; }

        #pragma unroll 4
        for (int kk = 0; kk < 32; ++kk) {
            const int k4 = k4lo + kk;
            const ulonglong2 w0 = *reinterpret_cast<const ulonglong2*>(
                &g_Wp0[(k4 * Hh + colbase + lane) * 4]);
            const ulonglong2 w1 = *reinterpret_cast<const ulonglong2*>(
                &g_Wp0[(k4 * Hh + colbase + lane + 32) * 4]);
            #pragma unroll
            for (int r = 0; r < 8; ++r) {
                ulonglong2 h = *reinterpret_cast<const ulonglong2*>(
                    &S.h0[8 * rg + r][k4 * 4]);
                a0[r] = f32x2_fma(h.x, w0.x, a0[r]);
                a0[r] = f32x2_fma(h.y, w0.y, a0[r]);
                a1[r] = f32x2_fma(h.x, w1.x, a1[r]);
                a1[r] = f32x2_fma(h.y, w1.y, a1[r]);
            }
        }
        #pragma unroll
        for (int r = 0; r < 8; ++r) {
            F2U u0; u0.u = a0[r];
            S.part[kg][8 * rg + r][lane] = u0.f.x + u0.f.y;
            F2U u1; u1.u = a1[r];
            S.part[kg][8 * rg + r][lane + 32] = u1.f.x + u1.f.y;
        }
        __syncthreads();           // parts visible; this CTA done reading h0
        cl_arrive();               // tell cluster: done reading h0

        // reduce into regs (overlaps peers' arrival)
        float4 v[2];
        {
            const float4 wv = *reinterpret_cast<const float4*>(&S.wih0s[4 * q]);
            const float4 bv = *reinterpret_cast<const float4*>(&S.bias0s[4 * q]);
            #pragma unroll
            for (int rr = 0; rr < 2; ++rr) {
                const int r = 2 * p + rr;
                float4 pa = *reinterpret_cast<const float4*>(&S.part[0][r][4 * q]);
                float4 pb = *reinterpret_cast<const float4*>(&S.part[1][r][4 * q]);
                const float xv = rr ? xv1 : xv0;
                v[rr].x = tanhf(xv * wv.x + bv.x + pa.x + pb.x);
                v[rr].y = tanhf(xv * wv.y + bv.y + pa.y + pb.y);
                v[rr].z = tanhf(xv * wv.z + bv.z + pa.z + pb.z);
                v[rr].w = tanhf(xv * wv.w + bv.w + pa.w + pb.w);
            }
        }
        cl_wait();                 // all CTAs done reading h0 -> safe to write
        #pragma unroll
        for (int rr = 0; rr < 2; ++rr) {
            uint32_t la = smem_u32(&S.h0[2 * p + rr][colbase + 4 * q]);
            #pragma unroll
            for (uint32_t pe = 0; pe < CLW; ++pe) dsmem_st128(la, pe, v[rr]);
        }
        cl_arrive(); cl_wait();    // h0' visible cluster-wide

        // ===== layer 1 partials (weights from smem) ======================
        #pragma unroll
        for (int r = 0; r < 8; ++r) { a0[r] = 0ULL; a1[r] = 0ULL; }

        #pragma unroll 2
        for (int kk = 0; kk < 32; ++kk) {
            const int k4 = k4lo + kk;
            const ulonglong2 wa0 = *reinterpret_cast<const ulonglong2*>(
                &S.wa[k4][lane][0]);
            const ulonglong2 wa1 = *reinterpret_cast<const ulonglong2*>(
                &S.wa[k4][lane + 32][0]);
            const ulonglong2 wb0 = *reinterpret_cast<const ulonglong2*>(
                &S.wb[k4][lane][0]);
            const ulonglong2 wb1 = *reinterpret_cast<const ulonglong2*>(
                &S.wb[k4][lane + 32][0]);
            #pragma unroll
            for (int r = 0; r < 8; ++r) {
                ulonglong2 ha = *reinterpret_cast<const ulonglong2*>(
                    &S.h0[8 * rg + r][k4 * 4]);
                ulonglong2 hb = *reinterpret_cast<const ulonglong2*>(
                    &S.h1[8 * rg + r][k4 * 4]);
                a0[r] = f32x2_fma(ha.x, wa0.x, a0[r]);
                a0[r] = f32x2_fma(ha.y, wa0.y, a0[r]);
                a0[r] = f32x2_fma(hb.x, wb0.x, a0[r]);
                a0[r] = f32x2_fma(hb.y, wb0.y, a0[r]);
                a1[r] = f32x2_fma(ha.x, wa1.x, a1[r]);
                a1[r] = f32x2_fma(ha.y, wa1.y, a1[r]);
                a1[r] = f32x2_fma(hb.x, wb1.x, a1[r]);
                a1[r] = f32x2_fma(hb.y, wb1.y, a1[r]);
            }
        }
        #pragma unroll
        for (int r = 0; r < 8; ++r) {
            F2U u0; u0.u = a0[r];
            S.part[kg][8 * rg + r][lane] = u0.f.x + u0.f.y;
            F2U u1; u1.u = a1[r];
            S.part[kg][8 * rg + r][lane + 32] = u1.f.x + u1.f.y;
        }
        __syncthreads();
        cl_arrive();

        {
            const float4 bv = *reinterpret_cast<const float4*>(&S.bias1s[4 * q]);
            #pragma unroll
            for (int rr = 0; rr < 2; ++rr) {
                const int r = 2 * p + rr;
                float4 pa = *reinterpret_cast<const float4*>(&S.part[0][r][4 * q]);
                float4 pb = *reinterpret_cast<const float4*>(&S.part[1][r][4 * q]);
                v[rr].x = tanhf(bv.x + pa.x + pb.x);
                v[rr].y = tanhf(bv.y + pa.y + pb.y);
                v[rr].z = tanhf(bv.z + pa.z + pb.z);
                v[rr].w = tanhf(bv.w + pa.w + pb.w);
            }
        }
        cl_wait();
        #pragma unroll
        for (int rr = 0; rr < 2; ++rr) {
            uint32_t la = smem_u32(&S.h1[2 * p + rr][colbase + 4 * q]);
            #pragma unroll
            for (uint32_t pe = 0; pe < CLW; ++pe) dsmem_st128(la, pe, v[rr]);
        }
        cl_arrive(); cl_wait();    // h1' visible cluster-wide
    }

    // ---- final FC: rank 0 writes the cluster's 32 rows ------------------
    if (rank == 0 && t < Cc * MBc) {
        int c = t >> 5, r = t & 31;
        float s = b_fc[c];
        #pragma unroll 8
        for (int h = 0; h < Hh; ++h)
            s += S.h1[r][h] * W_fc[c * Hh + h];
        out[(b0 + r) * Cc + c] = s;
    }
}

extern "C" void kernel_launch(void* const* d_in, const int* in_sizes, int n_in,
                              void* d_out, int out_size) {
    const float* x     = (const float*)d_in[0];
    const float* W_ih0 = (const float*)d_in[1];
    const float* W_hh0 = (const float*)d_in[2];
    const float* b_ih0 = (const float*)d_in[3];
    const float* b_hh0 = (const float*)d_in[4];
    const float* W_ih1 = (const float*)d_in[5];
    const float* W_hh1 = (const float*)d_in[6];
    const float* b_ih1 = (const float*)d_in[7];
    const float* b_hh1 = (const float*)d_in[8];
    const float* W_fc  = (const float*)d_in[9];
    const float* b_fc  = (const float*)d_in[10];
    float* out = (float*)d_out;

    cudaFuncSetAttribute(rnn_cl4_kernel,
                         cudaFuncAttributeMaxDynamicSharedMemorySize,
                         (int)sizeof(Smem));
    pack_kernel<<<Hh, Hh>>>(W_hh0, W_ih1, W_hh1);
    rnn_cl4_kernel<<<NCTA, THR, sizeof(Smem)>>>(
        x, W_ih0, b_ih0, b_hh0, b_ih1, b_hh1, W_fc, b_fc, out);
}

// round 16
// speedup vs baseline: 1.2572x; 1.2572x over previous
#include <cuda_runtime.h>

#define Hh 256
#define Tt 187
#define Bb 1024
#define Cc 5
#define MB 8
#define NCTA (Bb / MB)   // 128 CTAs, 1 per SM
#define THR 512          // 16 warps = colgroup(2) x kg(8)

// Packed weights: [k/4][j][4] so lane j loads 16B of 4 consecutive k's,
// coalesced across lanes (lanes = consecutive j).
__device__ float g_Wp0[Hh * Hh];
__device__ float g_Wpih1[Hh * Hh];
__device__ float g_Wp1[Hh * Hh];

__global__ void pack_kernel(const float* __restrict__ W_hh0,
                            const float* __restrict__ W_ih1,
                            const float* __restrict__ W_hh1) {
    int j = blockIdx.x, k = threadIdx.x;
    int src = j * Hh + k;
    int dst = ((k >> 2) * Hh + j) * 4 + (k & 3);
    g_Wp0[dst]   = W_hh0[src];
    g_Wpih1[dst] = W_ih1[src];
    g_Wp1[dst]   = W_hh1[src];
}

union F2U { unsigned long long u; float2 f; };

__device__ __forceinline__ unsigned long long f32x2_fma(
    unsigned long long a, unsigned long long b, unsigned long long c) {
    unsigned long long d;
    asm("fma.rn.f32x2 %0, %1, %2, %3;" : "=l"(d) : "l"(a), "l"(b), "l"(c));
    return d;
}

struct Smem {
    float part[8][MB][Hh];       // 64 KB  [kg][row][col]
    float h0[MB][Hh];            // 8 KB (in-place; barriers order RAW)
    float h1[MB][Hh];            // 8 KB
    float xs[MB][Tt + 1];        // ~6 KB
    float wih0s[Hh], bias0s[Hh], bias1s[Hh];   // 3 KB
};                               // ~89 KB

__global__ void __launch_bounds__(THR, 1) rnn_fused_kernel(
    const float* __restrict__ x,
    const float* __restrict__ W_ih0,
    const float* __restrict__ b_ih0, const float* __restrict__ b_hh0,
    const float* __restrict__ b_ih1, const float* __restrict__ b_hh1,
    const float* __restrict__ W_fc,  const float* __restrict__ b_fc,
    float* __restrict__ out)
{
    extern __shared__ __align__(16) char raw[];
    Smem& S = *reinterpret_cast<Smem*>(raw);

    const int t    = threadIdx.x;
    const int lane = t & 31;
    const int w    = t >> 5;
    const int cg   = w & 1;            // column group: cols [128cg, 128cg+128)
    const int kg   = w >> 1;           // k-group 0..7: k4 in [8kg, 8kg+8)
    const int c0   = cg * 128 + lane;  // cols c0 + {0,32,64,96}
    const int b0   = blockIdx.x * MB;

    for (int i = t; i < MB * Tt; i += THR) {
        int r = i / Tt, c = i % Tt;
        S.xs[r][c] = x[(b0 + r) * Tt + c];
    }
    for (int i = t; i < Hh; i += THR) {
        S.wih0s[i]  = W_ih0[i];
        S.bias0s[i] = b_ih0[i] + b_hh0[i];
        S.bias1s[i] = b_ih1[i] + b_hh1[i];
    }
    for (int i = t; i < MB * Hh; i += THR) {
        (&S.h0[0][0])[i] = 0.f;
        (&S.h1[0][0])[i] = 0.f;
    }
    __syncthreads();

    const int k4lo = kg * 8;

    for (int step = 0; step < Tt; ++step) {
        // ===== layer 0 partials: 8 rows x 4 cols over k-slice of 32 ======
        {
            unsigned long long acc[MB][4];
            #pragma unroll
            for (int r = 0; r < MB; ++r)
                #pragma unroll
                for (int c = 0; c < 4; ++c) acc[r][c] = 0ULL;

            #pragma unroll 4
            for (int kk = 0; kk < 8; ++kk) {
                const int k4 = k4lo + kk;
                ulonglong2 wv[4];
                #pragma unroll
                for (int c = 0; c < 4; ++c)
                    wv[c] = *reinterpret_cast<const ulonglong2*>(
                        &g_Wp0[(k4 * Hh + c0 + 32 * c) * 4]);
                #pragma unroll
                for (int r = 0; r < MB; ++r) {
                    ulonglong2 h = *reinterpret_cast<const ulonglong2*>(
                        &S.h0[r][k4 * 4]);
                    #pragma unroll
                    for (int c = 0; c < 4; ++c) {
                        acc[r][c] = f32x2_fma(h.x, wv[c].x, acc[r][c]);
                        acc[r][c] = f32x2_fma(h.y, wv[c].y, acc[r][c]);
                    }
                }
            }
            #pragma unroll
            for (int r = 0; r < MB; ++r)
                #pragma unroll
                for (int c = 0; c < 4; ++c) {
                    F2U u; u.u = acc[r][c];
                    S.part[kg][r][c0 + 32 * c] = u.f.x + u.f.y;
                }
        }
        __syncthreads();

        // ===== layer 0 reduce + tanh: 2048 outputs / 512 threads =========
        #pragma unroll
        for (int i = 0; i < 4; ++i) {
            int idx = t + THR * i;
            int col = idx & 255, b = idx >> 8;
            float s = ((S.part[0][b][col] + S.part[1][b][col])
                     + (S.part[2][b][col] + S.part[3][b][col]))
                    + ((S.part[4][b][col] + S.part[5][b][col])
                     + (S.part[6][b][col] + S.part[7][b][col]));
            float pre = S.xs[b][step] * S.wih0s[col] + S.bias0s[col] + s;
            S.h0[b][col] = tanhf(pre);
        }
        __syncthreads();

        // ===== layer 1 partials ==========================================
        {
            unsigned long long acc[MB][4];
            #pragma unroll
            for (int r = 0; r < MB; ++r)
                #pragma unroll
                for (int c = 0; c < 4; ++c) acc[r][c] = 0ULL;

            #pragma unroll 2
            for (int kk = 0; kk < 8; ++kk) {
                const int k4 = k4lo + kk;
                ulonglong2 wa[4], wb[4];
                #pragma unroll
                for (int c = 0; c < 4; ++c) {
                    wa[c] = *reinterpret_cast<const ulonglong2*>(
                        &g_Wpih1[(k4 * Hh + c0 + 32 * c) * 4]);
                    wb[c] = *reinterpret_cast<const ulonglong2*>(
                        &g_Wp1[(k4 * Hh + c0 + 32 * c) * 4]);
                }
                #pragma unroll
                for (int r = 0; r < MB; ++r) {
                    ulonglong2 ha = *reinterpret_cast<const ulonglong2*>(
                        &S.h0[r][k4 * 4]);
                    ulonglong2 hb = *reinterpret_cast<const ulonglong2*>(
                        &S.h1[r][k4 * 4]);
                    #pragma unroll
                    for (int c = 0; c < 4; ++c) {
                        acc[r][c] = f32x2_fma(ha.x, wa[c].x, acc[r][c]);
                        acc[r][c] = f32x2_fma(ha.y, wa[c].y, acc[r][c]);
                        acc[r][c] = f32x2_fma(hb.x, wb[c].x, acc[r][c]);
                        acc[r][c] = f32x2_fma(hb.y, wb[c].y, acc[r][c]);
                    }
                }
            }
            #pragma unroll
            for (int r = 0; r < MB; ++r)
                #pragma unroll
                for (int c = 0; c < 4; ++c) {
                    F2U u; u.u = acc[r][c];
                    S.part[kg][r][c0 + 32 * c] = u.f.x + u.f.y;
                }
        }
        __syncthreads();

        // ===== layer 1 reduce + tanh =====================================
        #pragma unroll
        for (int i = 0; i < 4; ++i) {
            int idx = t + THR * i;
            int col = idx & 255, b = idx >> 8;
            float s = ((S.part[0][b][col] + S.part[1][b][col])
                     + (S.part[2][b][col] + S.part[3][b][col]))
                    + ((S.part[4][b][col] + S.part[5][b][col])
                     + (S.part[6][b][col] + S.part[7][b][col]));
            S.h1[b][col] = tanhf(S.bias1s[col] + s);
        }
        __syncthreads();
    }

    // ---- final FC: out[b] = h1_last @ W_fc^T + b_fc ---------------------
    if (t < Cc * MB) {
        int c = t / MB, b = t % MB;
        float s = b_fc[c];
        #pragma unroll 8
        for (int h = 0; h < Hh; ++h)
            s += S.h1[b][h] * W_fc[c * Hh + h];
        out[(b0 + b) * Cc + c] = s;
    }
}

extern "C" void kernel_launch(void* const* d_in, const int* in_sizes, int n_in,
                              void* d_out, int out_size) {
    const float* x     = (const float*)d_in[0];
    const float* W_ih0 = (const float*)d_in[1];
    const float* W_hh0 = (const float*)d_in[2];
    const float* b_ih0 = (const float*)d_in[3];
    const float* b_hh0 = (const float*)d_in[4];
    const float* W_ih1 = (const float*)d_in[5];
    const float* W_hh1 = (const float*)d_in[6];
    const float* b_ih1 = (const float*)d_in[7];
    const float* b_hh1 = (const float*)d_in[8];
    const float* W_fc  = (const float*)d_in[9];
    const float* b_fc  = (const float*)d_in[10];
    float* out = (float*)d_out;

    cudaFuncSetAttribute(rnn_fused_kernel,
                         cudaFuncAttributeMaxDynamicSharedMemorySize,
                         (int)sizeof(Smem));
    pack_kernel<<<Hh, Hh>>>(W_hh0, W_ih1, W_hh1);
    rnn_fused_kernel<<<NCTA, THR, sizeof(Smem)>>>(
        x, W_ih0, b_ih0, b_hh0, b_ih1, b_hh1, W_fc, b_fc, out);
}